// round 5
// baseline (speedup 1.0000x reference)
#include <cuda_runtime.h>
#include <cuda_fp16.h>
#include <math.h>

#define NNODES 100000
#define DIN 256
#define DOUT 64
#define NEDGE 3200000
#define SCAN_BLK 1024
#define NB ((NNODES + SCAN_BLK - 1) / SCAN_BLK)   // 98

// ---------------- scratch (device globals; no allocation allowed) ----------------
__device__ float   g_self_p[NNODES * DOUT];    // x_p @ w_self_p          (fp32, exact)
__device__ float   g_self_a[NNODES * DOUT];    // x_a @ w_self_a
__device__ __half2 g_rels_p[NNODES * DOUT/2];  // x_p @ w_rel_a_p  (fp16, gather table)
__device__ __half2 g_rels_a[NNODES * DOUT/2];  // x_a @ w_rel_p_a
__device__ float   g_nb_p[NNODES * DOUT];      // aggregated neighbor feats (interleaved)
__device__ float   g_nb_a[NNODES * DOUT];
__device__ float   g_vkq[4 * DOUT];

// CSR build scratch (2 relations)
__device__ int  g_cnt[2][NNODES];
__device__ int  g_off[2][NNODES];
__device__ int  g_cur[2][NNODES];
__device__ int  g_bsum[2][NB + 1];
__device__ int2 g_edge[2][NEDGE];              // packed {col, val-bits}

// ---------------- fold attention projections into 64-vectors ----------------
__global__ void vkq_kernel(const float* __restrict__ wk_p, const float* __restrict__ wq_p,
                           const float* __restrict__ wa_p,
                           const float* __restrict__ wk_a, const float* __restrict__ wq_a,
                           const float* __restrict__ wa_a) {
    int t = threadIdx.x;
    if (t >= 4 * DOUT) return;
    int which = t >> 6, d = t & 63;
    const float* W; const float* a;
    if (which == 0)      { W = wk_p; a = wa_p; }
    else if (which == 1) { W = wq_p; a = wa_p + DOUT; }
    else if (which == 2) { W = wk_a; a = wa_a; }
    else                 { W = wq_a; a = wa_a + DOUT; }
    float s = 0.f;
#pragma unroll 16
    for (int i = 0; i < DOUT; i++) s += W[d * DOUT + i] * a[i];
    g_vkq[which * DOUT + d] = s;
}

// ---------------- CSR build ----------------
__global__ void zero_cnt_kernel() {
    int i = blockIdx.x * blockDim.x + threadIdx.x;
    if (i < 2 * NNODES) ((int*)g_cnt)[i] = 0;
}

__global__ void hist_kernel(const int* __restrict__ row, int* __restrict__ cnt) {
    int e = blockIdx.x * blockDim.x + threadIdx.x;
    if (e < NEDGE) atomicAdd(cnt + __ldg(row + e), 1);   // no return use -> RED
}

__global__ void scan1_kernel(const int* __restrict__ cnt, int* __restrict__ off,
                             int* __restrict__ bsum) {
    __shared__ int s[SCAN_BLK];
    int t = threadIdx.x;
    int i = blockIdx.x * SCAN_BLK + t;
    int v = (i < NNODES) ? cnt[i] : 0;
    s[t] = v;
    __syncthreads();
#pragma unroll
    for (int o = 1; o < SCAN_BLK; o <<= 1) {
        int x = (t >= o) ? s[t - o] : 0;
        __syncthreads();
        s[t] += x;
        __syncthreads();
    }
    if (i < NNODES) off[i] = s[t] - v;      // exclusive within block
    if (t == SCAN_BLK - 1) bsum[blockIdx.x] = s[t];
}

__global__ void scan2_kernel(int* __restrict__ bsum) {
    __shared__ int s[128];
    int t = threadIdx.x;
    int v = (t < NB) ? bsum[t] : 0;
    s[t] = v;
    __syncthreads();
#pragma unroll
    for (int o = 1; o < 128; o <<= 1) {
        int x = (t >= o) ? s[t - o] : 0;
        __syncthreads();
        s[t] += x;
        __syncthreads();
    }
    if (t < NB) bsum[t] = s[t] - v;          // exclusive
}

__global__ void scan3_kernel(int* __restrict__ off, int* __restrict__ cur,
                             const int* __restrict__ bsum) {
    int i = blockIdx.x * blockDim.x + threadIdx.x;
    if (i < NNODES) {
        int o = off[i] + bsum[i >> 10];
        off[i] = o;
        cur[i] = o;
    }
}

__global__ void scatter_kernel(const int* __restrict__ row, const int* __restrict__ col,
                               const float* __restrict__ val, int* __restrict__ cur,
                               int2* __restrict__ edges) {
    int e = blockIdx.x * blockDim.x + threadIdx.x;
    if (e >= NEDGE) return;
    int r = __ldg(row + e);
    int pos = atomicAdd(cur + r, 1);
    edges[pos] = make_int2(__ldg(col + e), __float_as_int(__ldg(val + e)));
}

// ---------------- gather SpMM: warp per dst node, smem-staged edges ----------------
// Edges for the warp's node are cooperatively loaded into smem (one coalesced LDG per
// 32-edge batch), then consumed in unrolled groups of 8 so the 8 gathers are
// independent and in flight together (MLP=8 per warp). Padding edges have v=+0 and
// gather row 0 (harmless, exact).
__global__ __launch_bounds__(256) void spmm_nb_kernel(
    const int* __restrict__ off, const int* __restrict__ cnt, const int2* __restrict__ edges,
    const __half2* __restrict__ src, float* __restrict__ nb)
{
    __shared__ int2 se[8][32];
    int wid = threadIdx.x >> 5;
    int lane = threadIdx.x & 31;
    int gw = blockIdx.x * 8 + wid;
    if (gw >= NNODES) return;
    int start = __ldg(off + gw);
    int deg   = __ldg(cnt + gw);
    int2* myse = se[wid];

    float a0 = 0.f, a1 = 0.f, b0 = 0.f, b1 = 0.f;

    for (int base = 0; base < deg; base += 32) {
        int n = deg - base; if (n > 32) n = 32;
        myse[lane] = (lane < n) ? __ldg(edges + start + base + lane) : make_int2(0, 0);
        __syncwarp();
#pragma unroll
        for (int j0 = 0; j0 < 32; j0 += 8) {
            if (j0 < n) {
                int2 e[8];
#pragma unroll
                for (int u = 0; u < 8; u++) e[u] = myse[j0 + u];
                __half2 h[8];
#pragma unroll
                for (int u = 0; u < 8; u++)
                    h[u] = __ldg(src + (size_t)e[u].x * 32 + lane);
#pragma unroll
                for (int u = 0; u < 8; u++) {
                    float2 f = __half22float2(h[u]);
                    float v = __int_as_float(e[u].y);
                    if (u & 1) { b0 = fmaf(v, f.x, b0); b1 = fmaf(v, f.y, b1); }
                    else       { a0 = fmaf(v, f.x, a0); a1 = fmaf(v, f.y, a1); }
                }
            }
        }
        __syncwarp();
    }
    a0 += b0; a1 += b1;
    *(float2*)(nb + (size_t)gw * DOUT + 2 * lane) = make_float2(a0, a1);
}

// ---------------- attention mix + output, warp per node (interleaved layout) --------
__global__ __launch_bounds__(256) void finalize_kernel(
    const float* __restrict__ selfft, const float* __restrict__ nbft,
    const float* __restrict__ bias, const float* __restrict__ vk, const float* __restrict__ vq,
    float* __restrict__ out, float* __restrict__ att)
{
    int gw = (blockIdx.x * blockDim.x + threadIdx.x) >> 5;
    int lane = threadIdx.x & 31;
    if (gw >= NNODES) return;
    size_t base = (size_t)gw * DOUT;

    float2 s = *(const float2*)(selfft + base + 2 * lane);
    float2 n = *(const float2*)(nbft + base + 2 * lane);
    float2 k = *(const float2*)(vk + 2 * lane);
    float2 q = *(const float2*)(vq + 2 * lane);
    float2 b = *(const float2*)(bias + 2 * lane);

    float d_skq = s.x * (k.x + q.x) + s.y * (k.y + q.y);
    float d_sq  = s.x * q.x + s.y * q.y;
    float d_nk  = n.x * k.x + n.y * k.y;
#pragma unroll
    for (int o = 16; o; o >>= 1) {
        d_skq += __shfl_xor_sync(0xffffffffu, d_skq, o);
        d_sq  += __shfl_xor_sync(0xffffffffu, d_sq,  o);
        d_nk  += __shfl_xor_sync(0xffffffffu, d_nk,  o);
    }
    float e0v = d_skq;
    float e1v = d_nk + d_sq;
    e0v = (e0v > 0.f) ? e0v : expm1f(e0v);   // elu
    e1v = (e1v > 0.f) ? e1v : expm1f(e1v);
    float m = fmaxf(e0v, e1v);
    float a0 = expf(e0v - m), a1 = expf(e1v - m);
    float inv = 1.f / (a0 + a1);
    a0 *= inv; a1 *= inv;

    float2 o2 = make_float2(fmaf(a0, s.x, fmaf(a1, n.x, b.x)),
                            fmaf(a0, s.y, fmaf(a1, n.y, b.y)));
    *(float2*)(out + base + 2 * lane) = o2;
    if (lane == 0) { att[(size_t)gw * 2] = a0; att[(size_t)gw * 2 + 1] = a1; }
}

// ---------------- fused dual-weight GEMM with packed f32x2 FMA ----------------
// Cs (self path) stored fp32; Cr (rel path) stored fp16 for the SpMM gather.
#define BM 64
#define BN 128
#define BK 16

union F2 { float2 f; unsigned long long u; };
union H8 { __half2 h[4]; uint4 u; };

__global__ __launch_bounds__(128) void gemm_dual_kernel(
    const float* __restrict__ X, const float* __restrict__ Ws, const float* __restrict__ Wr,
    float* __restrict__ Cs, __half* __restrict__ Cr, int nrows)
{
    __shared__ float As[BK][BM];        // transposed tile: As[k][m]
    __shared__ float Bs[BK][BN];

    const int tid = threadIdx.x;        // 0..127
    const int block_row = blockIdx.x * BM;
    const int rg = tid >> 4;            // 0..7  (row group of 8)
    const int cg = tid & 15;            // 0..15 (col group of 8)

    F2 acc[4][8];
#pragma unroll
    for (int i = 0; i < 4; i++)
#pragma unroll
        for (int j = 0; j < 8; j++) acc[i][j].u = 0ULL;

    for (int k0 = 0; k0 < DIN; k0 += BK) {
#pragma unroll
        for (int i = tid; i < BM * BK / 4; i += 128) {
            int m = i >> 2, kq = i & 3;
            int r = block_row + m;
            float4 v = make_float4(0.f, 0.f, 0.f, 0.f);
            if (r < nrows)
                v = *(const float4*)(X + (size_t)r * DIN + k0 + kq * 4);
            As[kq * 4 + 0][m] = v.x;
            As[kq * 4 + 1][m] = v.y;
            As[kq * 4 + 2][m] = v.z;
            As[kq * 4 + 3][m] = v.w;
        }
#pragma unroll
        for (int i = tid; i < BK * BN / 4; i += 128) {
            int k = i >> 5;
            int c4 = i & 31;
            float4 v;
            if (c4 < 16) v = *(const float4*)(Ws + (size_t)(k0 + k) * DOUT + c4 * 4);
            else         v = *(const float4*)(Wr + (size_t)(k0 + k) * DOUT + (c4 - 16) * 4);
            *(float4*)&Bs[k][c4 * 4] = v;
        }
        __syncthreads();

#pragma unroll
        for (int k = 0; k < BK; k++) {
            float4 a0 = *(const float4*)&As[k][rg * 8];
            float4 a1 = *(const float4*)&As[k][rg * 8 + 4];
            float4 b0 = *(const float4*)&Bs[k][cg * 8];
            float4 b1 = *(const float4*)&Bs[k][cg * 8 + 4];

            F2 ap[4];
            ap[0].f = make_float2(a0.x, a0.y);
            ap[1].f = make_float2(a0.z, a0.w);
            ap[2].f = make_float2(a1.x, a1.y);
            ap[3].f = make_float2(a1.z, a1.w);

            float bv[8] = {b0.x, b0.y, b0.z, b0.w, b1.x, b1.y, b1.z, b1.w};
#pragma unroll
            for (int j = 0; j < 8; j++) {
                F2 bd; bd.f = make_float2(bv[j], bv[j]);
#pragma unroll
                for (int ip = 0; ip < 4; ip++) {
                    asm("fma.rn.f32x2 %0, %1, %2, %3;"
                        : "=l"(acc[ip][j].u)
                        : "l"(ap[ip].u), "l"(bd.u), "l"(acc[ip][j].u));
                }
            }
        }
        __syncthreads();
    }

    const int cbase = cg * 8;
    if (cbase < 64) {
        const int ccol = cbase;
#pragma unroll
        for (int ip = 0; ip < 4; ip++) {
            int r0 = block_row + rg * 8 + 2 * ip;
            int r1 = r0 + 1;
            if (r0 < nrows) {
                *(float4*)(Cs + (size_t)r0 * DOUT + ccol) =
                    make_float4(acc[ip][0].f.x, acc[ip][1].f.x, acc[ip][2].f.x, acc[ip][3].f.x);
                *(float4*)(Cs + (size_t)r0 * DOUT + ccol + 4) =
                    make_float4(acc[ip][4].f.x, acc[ip][5].f.x, acc[ip][6].f.x, acc[ip][7].f.x);
            }
            if (r1 < nrows) {
                *(float4*)(Cs + (size_t)r1 * DOUT + ccol) =
                    make_float4(acc[ip][0].f.y, acc[ip][1].f.y, acc[ip][2].f.y, acc[ip][3].f.y);
                *(float4*)(Cs + (size_t)r1 * DOUT + ccol + 4) =
                    make_float4(acc[ip][4].f.y, acc[ip][5].f.y, acc[ip][6].f.y, acc[ip][7].f.y);
            }
        }
    } else {
        const int ccol = cbase - 64;
#pragma unroll
        for (int ip = 0; ip < 4; ip++) {
            int r0 = block_row + rg * 8 + 2 * ip;
            int r1 = r0 + 1;
            if (r0 < nrows) {
                H8 p;
                p.h[0] = __floats2half2_rn(acc[ip][0].f.x, acc[ip][1].f.x);
                p.h[1] = __floats2half2_rn(acc[ip][2].f.x, acc[ip][3].f.x);
                p.h[2] = __floats2half2_rn(acc[ip][4].f.x, acc[ip][5].f.x);
                p.h[3] = __floats2half2_rn(acc[ip][6].f.x, acc[ip][7].f.x);
                *(uint4*)(Cr + (size_t)r0 * DOUT + ccol) = p.u;
            }
            if (r1 < nrows) {
                H8 p;
                p.h[0] = __floats2half2_rn(acc[ip][0].f.y, acc[ip][1].f.y);
                p.h[1] = __floats2half2_rn(acc[ip][2].f.y, acc[ip][3].f.y);
                p.h[2] = __floats2half2_rn(acc[ip][4].f.y, acc[ip][5].f.y);
                p.h[3] = __floats2half2_rn(acc[ip][6].f.y, acc[ip][7].f.y);
                *(uint4*)(Cr + (size_t)r1 * DOUT + ccol) = p.u;
            }
        }
    }
}

// ---------------- launch ----------------
extern "C" void kernel_launch(void* const* d_in, const int* in_sizes, int n_in,
                              void* d_out, int out_size) {
    const float* x_p       = (const float*)d_in[0];
    const float* x_a       = (const float*)d_in[1];
    const int*   adj_a_row = (const int*)d_in[2];
    const int*   adj_a_col = (const int*)d_in[3];
    const float* adj_a_val = (const float*)d_in[4];
    const int*   adj_p_row = (const int*)d_in[5];
    const int*   adj_p_col = (const int*)d_in[6];
    const float* adj_p_val = (const float*)d_in[7];
    const float* w_self_p  = (const float*)d_in[8];
    const float* w_rel_p_a = (const float*)d_in[9];
    const float* bias_p    = (const float*)d_in[10];
    const float* w_query_p = (const float*)d_in[11];
    const float* w_keys_p  = (const float*)d_in[12];
    const float* w_att_p   = (const float*)d_in[13];
    const float* w_self_a  = (const float*)d_in[14];
    const float* w_rel_a_p = (const float*)d_in[15];
    const float* bias_a    = (const float*)d_in[16];
    const float* w_query_a = (const float*)d_in[17];
    const float* w_keys_a  = (const float*)d_in[18];
    const float* w_att_a   = (const float*)d_in[19];

    float* out = (float*)d_out;
    float* out_p = out;
    float* out_a = out + (size_t)NNODES * DOUT;
    float* att_p = out + (size_t)2 * NNODES * DOUT;
    float* att_a = att_p + (size_t)NNODES * 2;

    float *p_self_p, *p_self_a, *p_nb_p, *p_nb_a, *p_vkq;
    __half2 *p_rels_p, *p_rels_a;
    int *p_cnt, *p_off, *p_cur, *p_bsum;
    int2 *p_edge;
    cudaGetSymbolAddress((void**)&p_self_p, g_self_p);
    cudaGetSymbolAddress((void**)&p_self_a, g_self_a);
    cudaGetSymbolAddress((void**)&p_rels_p, g_rels_p);
    cudaGetSymbolAddress((void**)&p_rels_a, g_rels_a);
    cudaGetSymbolAddress((void**)&p_nb_p, g_nb_p);
    cudaGetSymbolAddress((void**)&p_nb_a, g_nb_a);
    cudaGetSymbolAddress((void**)&p_vkq, g_vkq);
    cudaGetSymbolAddress((void**)&p_cnt, g_cnt);
    cudaGetSymbolAddress((void**)&p_off, g_off);
    cudaGetSymbolAddress((void**)&p_cur, g_cur);
    cudaGetSymbolAddress((void**)&p_bsum, g_bsum);
    cudaGetSymbolAddress((void**)&p_edge, g_edge);

    static cudaStream_t s1 = nullptr;
    static cudaEvent_t e_fork = nullptr, e_build = nullptr, e_ga = nullptr,
                       e_gp = nullptr, e_sp = nullptr;
    if (s1 == nullptr) {
        cudaStreamCreateWithFlags(&s1, cudaStreamNonBlocking);
        cudaEventCreateWithFlags(&e_fork, cudaEventDisableTiming);
        cudaEventCreateWithFlags(&e_build, cudaEventDisableTiming);
        cudaEventCreateWithFlags(&e_ga, cudaEventDisableTiming);
        cudaEventCreateWithFlags(&e_gp, cudaEventDisableTiming);
        cudaEventCreateWithFlags(&e_sp, cudaEventDisableTiming);
    }

    const int EB = (NEDGE + 255) / 256;
    const int NBK = (NNODES + 255) / 256;
    const int gblocks = (NNODES + BM - 1) / BM;
    const int wblocks = (NNODES * 32 + 255) / 256;   // warp-per-node kernels

    // fork
    cudaEventRecord(e_fork, 0);
    cudaStreamWaitEvent(s1, e_fork, 0);

    // ---- s1: attention fold + CSR build for both relations ----
    vkq_kernel<<<1, 256, 0, s1>>>(w_keys_p, w_query_p, w_att_p, w_keys_a, w_query_a, w_att_a);
    zero_cnt_kernel<<<(2 * NNODES + 255) / 256, 256, 0, s1>>>();
    hist_kernel<<<EB, 256, 0, s1>>>(adj_a_row, p_cnt);
    hist_kernel<<<EB, 256, 0, s1>>>(adj_p_row, p_cnt + NNODES);
    for (int rel = 0; rel < 2; rel++) {
        scan1_kernel<<<NB, SCAN_BLK, 0, s1>>>(p_cnt + rel * NNODES, p_off + rel * NNODES,
                                              p_bsum + rel * (NB + 1));
        scan2_kernel<<<1, 128, 0, s1>>>(p_bsum + rel * (NB + 1));
        scan3_kernel<<<NBK, 256, 0, s1>>>(p_off + rel * NNODES, p_cur + rel * NNODES,
                                          p_bsum + rel * (NB + 1));
    }
    scatter_kernel<<<EB, 256, 0, s1>>>(adj_a_row, adj_a_col, adj_a_val, p_cur, p_edge);
    scatter_kernel<<<EB, 256, 0, s1>>>(adj_p_row, adj_p_col, adj_p_val, p_cur + NNODES,
                                       p_edge + NEDGE);
    cudaEventRecord(e_build, s1);

    // ---- s0: GEMM_a (produces self_a, rels_a) then GEMM_p ----
    gemm_dual_kernel<<<gblocks, 128>>>(x_a, w_self_a, w_rel_p_a, p_self_a, (__half*)p_rels_a,
                                       NNODES);
    cudaEventRecord(e_ga, 0);
    gemm_dual_kernel<<<gblocks, 128>>>(x_p, w_self_p, w_rel_a_p, p_self_p, (__half*)p_rels_p,
                                       NNODES);
    cudaEventRecord(e_gp, 0);

    // ---- s1: spmm_p (needs build + rels_a) — overlaps GEMM_p on s0 ----
    cudaStreamWaitEvent(s1, e_ga, 0);
    spmm_nb_kernel<<<(NNODES + 7) / 8, 256, 0, s1>>>(p_off, p_cnt, p_edge, p_rels_a, p_nb_p);
    cudaStreamWaitEvent(s1, e_gp, 0);
    finalize_kernel<<<wblocks, 256, 0, s1>>>(p_self_p, p_nb_p, bias_p,
                                             p_vkq + 0 * DOUT, p_vkq + 1 * DOUT, out_p, att_p);
    cudaEventRecord(e_sp, s1);

    // ---- s0: spmm_a (needs build + rels_p) + finalize_a ----
    cudaStreamWaitEvent(0, e_build, 0);
    spmm_nb_kernel<<<(NNODES + 7) / 8, 256>>>(p_off + NNODES, p_cnt + NNODES, p_edge + NEDGE,
                                              p_rels_p, p_nb_a);
    finalize_kernel<<<wblocks, 256>>>(p_self_a, p_nb_a, bias_a,
                                      p_vkq + 2 * DOUT, p_vkq + 3 * DOUT, out_a, att_a);

    // join s1 back into origin stream
    cudaStreamWaitEvent(0, e_sp, 0);
}

// round 6
// speedup vs baseline: 1.3476x; 1.3476x over previous
#include <cuda_runtime.h>
#include <cuda_fp16.h>
#include <math.h>

#define NNODES 100000
#define DIN 256
#define DOUT 64
#define NEDGE 3200000
#define SCAN_BLK 1024
#define NB ((NNODES + SCAN_BLK - 1) / SCAN_BLK)   // 98

// ---------------- scratch (device globals; no allocation allowed) ----------------
__device__ float   g_self_p[NNODES * DOUT];    // x_p @ w_self_p          (fp32, exact)
__device__ float   g_self_a[NNODES * DOUT];    // x_a @ w_self_a
__device__ __half2 g_rels_p[NNODES * DOUT/2];  // x_p @ w_rel_a_p  (fp16, gather table)
__device__ __half2 g_rels_a[NNODES * DOUT/2];  // x_a @ w_rel_p_a
__device__ float   g_nb_p[NNODES * DOUT];      // aggregated neighbor feats (interleaved)
__device__ float   g_nb_a[NNODES * DOUT];
__device__ float   g_vkq[4 * DOUT];

// CSR build scratch (2 relations)
__device__ int  g_cnt[2][NNODES];
__device__ int  g_off[2][NNODES];
__device__ int  g_cur[2][NNODES];
__device__ int  g_bsum[2][NB + 1];
__device__ int2 g_edge[2][NEDGE];              // packed {col, val-bits}

// ---------------- fold attention projections into 64-vectors ----------------
__global__ void vkq_kernel(const float* __restrict__ wk_p, const float* __restrict__ wq_p,
                           const float* __restrict__ wa_p,
                           const float* __restrict__ wk_a, const float* __restrict__ wq_a,
                           const float* __restrict__ wa_a) {
    int t = threadIdx.x;
    if (t >= 4 * DOUT) return;
    int which = t >> 6, d = t & 63;
    const float* W; const float* a;
    if (which == 0)      { W = wk_p; a = wa_p; }
    else if (which == 1) { W = wq_p; a = wa_p + DOUT; }
    else if (which == 2) { W = wk_a; a = wa_a; }
    else                 { W = wq_a; a = wa_a + DOUT; }
    float s = 0.f;
#pragma unroll 16
    for (int i = 0; i < DOUT; i++) s += W[d * DOUT + i] * a[i];
    g_vkq[which * DOUT + d] = s;
}

// ---------------- CSR build ----------------
__global__ void zero_cnt_kernel() {
    int i = blockIdx.x * blockDim.x + threadIdx.x;
    if (i < 2 * NNODES) ((int*)g_cnt)[i] = 0;
}

__global__ void hist_kernel(const int* __restrict__ row, int* __restrict__ cnt) {
    int e = blockIdx.x * blockDim.x + threadIdx.x;
    if (e < NEDGE) atomicAdd(cnt + __ldg(row + e), 1);   // no return use -> RED
}

__global__ void scan1_kernel(const int* __restrict__ cnt, int* __restrict__ off,
                             int* __restrict__ bsum) {
    __shared__ int s[SCAN_BLK];
    int t = threadIdx.x;
    int i = blockIdx.x * SCAN_BLK + t;
    int v = (i < NNODES) ? cnt[i] : 0;
    s[t] = v;
    __syncthreads();
#pragma unroll
    for (int o = 1; o < SCAN_BLK; o <<= 1) {
        int x = (t >= o) ? s[t - o] : 0;
        __syncthreads();
        s[t] += x;
        __syncthreads();
    }
    if (i < NNODES) off[i] = s[t] - v;      // exclusive within block
    if (t == SCAN_BLK - 1) bsum[blockIdx.x] = s[t];
}

__global__ void scan2_kernel(int* __restrict__ bsum) {
    __shared__ int s[128];
    int t = threadIdx.x;
    int v = (t < NB) ? bsum[t] : 0;
    s[t] = v;
    __syncthreads();
#pragma unroll
    for (int o = 1; o < 128; o <<= 1) {
        int x = (t >= o) ? s[t - o] : 0;
        __syncthreads();
        s[t] += x;
        __syncthreads();
    }
    if (t < NB) bsum[t] = s[t] - v;          // exclusive
}

__global__ void scan3_kernel(int* __restrict__ off, int* __restrict__ cur,
                             const int* __restrict__ bsum) {
    int i = blockIdx.x * blockDim.x + threadIdx.x;
    if (i < NNODES) {
        int o = off[i] + bsum[i >> 10];
        off[i] = o;
        cur[i] = o;
    }
}

__global__ void scatter_kernel(const int* __restrict__ row, const int* __restrict__ col,
                               const float* __restrict__ val, int* __restrict__ cur,
                               int2* __restrict__ edges) {
    int e = blockIdx.x * blockDim.x + threadIdx.x;
    if (e >= NEDGE) return;
    int r = __ldg(row + e);
    int pos = atomicAdd(cur + r, 1);
    edges[pos] = make_int2(__ldg(col + e), __float_as_int(__ldg(val + e)));
}

// ---------------- software-pipelined gather SpMM: warp per dst node ----------------
// Branch-free modulo-2 pipeline: edge loads run one 4-group ahead of gathers, gathers
// one group ahead of FMAs. Out-of-range edges are clamped to the last valid edge
// (L1-hot duplicate gather) with their value masked to +0.f, so every instruction in
// the loop body executes unconditionally (no BSSY/BSYNC barriers blocking overlap).
__device__ __forceinline__ void load_group4(const int2* __restrict__ edges, int start,
                                            int last, int g, int2 E[4], float V[4]) {
#pragma unroll
    for (int u = 0; u < 4; u++) {
        int i = start + 4 * g + u;
        int idx = min(i, last);
        int2 e = __ldg(edges + idx);
        E[u] = e;
        V[u] = (i <= last) ? __int_as_float(e.y) : 0.f;
    }
}

__global__ __launch_bounds__(256) void spmm_nb_kernel(
    const int* __restrict__ off, const int* __restrict__ cnt, const int2* __restrict__ edges,
    const __half2* __restrict__ src, float* __restrict__ nb)
{
    int gw = (blockIdx.x * blockDim.x + threadIdx.x) >> 5;
    int lane = threadIdx.x & 31;
    if (gw >= NNODES) return;
    int start = __ldg(off + gw);
    int deg   = __ldg(cnt + gw);

    float a0 = 0.f, a1 = 0.f, b0 = 0.f, b1 = 0.f;

    if (deg > 0) {
        int last  = start + deg - 1;
        int niter = (deg + 3) >> 2;

        int2 E[4], En[4];
        float V[4], Vn[4];
        __half2 H[4];
        float HV[4];

        // prologue: group 0 edges -> gathers; group 1 edges in flight
        load_group4(edges, start, last, 0, E, V);
#pragma unroll
        for (int u = 0; u < 4; u++) H[u] = __ldg(src + (size_t)E[u].x * 32 + lane);
#pragma unroll
        for (int u = 0; u < 4; u++) HV[u] = V[u];
        load_group4(edges, start, last, 1, En, Vn);   // clamped: safe for any niter

        for (int g = 1; g < niter; g++) {
            // gathers for group g (edge data arrived last iteration)
            __half2 Hn[4];
#pragma unroll
            for (int u = 0; u < 4; u++) Hn[u] = __ldg(src + (size_t)En[u].x * 32 + lane);
            float HVn[4];
#pragma unroll
            for (int u = 0; u < 4; u++) HVn[u] = Vn[u];
            // edge loads for group g+1 (clamped; harmless duplicate when past the end)
            load_group4(edges, start, last, g + 1, En, Vn);
            // consume group g-1 gathers (data arrived during previous iteration)
#pragma unroll
            for (int u = 0; u < 4; u++) {
                float2 f = __half22float2(H[u]);
                if (u & 1) { b0 = fmaf(HV[u], f.x, b0); b1 = fmaf(HV[u], f.y, b1); }
                else       { a0 = fmaf(HV[u], f.x, a0); a1 = fmaf(HV[u], f.y, a1); }
            }
#pragma unroll
            for (int u = 0; u < 4; u++) { H[u] = Hn[u]; HV[u] = HVn[u]; }
        }
        // epilogue: last group
#pragma unroll
        for (int u = 0; u < 4; u++) {
            float2 f = __half22float2(H[u]);
            if (u & 1) { b0 = fmaf(HV[u], f.x, b0); b1 = fmaf(HV[u], f.y, b1); }
            else       { a0 = fmaf(HV[u], f.x, a0); a1 = fmaf(HV[u], f.y, a1); }
        }
    }

    a0 += b0; a1 += b1;
    *(float2*)(nb + (size_t)gw * DOUT + 2 * lane) = make_float2(a0, a1);
}

// ---------------- attention mix + output, warp per node (interleaved layout) --------
__global__ __launch_bounds__(256) void finalize_kernel(
    const float* __restrict__ selfft, const float* __restrict__ nbft,
    const float* __restrict__ bias, const float* __restrict__ vk, const float* __restrict__ vq,
    float* __restrict__ out, float* __restrict__ att)
{
    int gw = (blockIdx.x * blockDim.x + threadIdx.x) >> 5;
    int lane = threadIdx.x & 31;
    if (gw >= NNODES) return;
    size_t base = (size_t)gw * DOUT;

    float2 s = *(const float2*)(selfft + base + 2 * lane);
    float2 n = *(const float2*)(nbft + base + 2 * lane);
    float2 k = *(const float2*)(vk + 2 * lane);
    float2 q = *(const float2*)(vq + 2 * lane);
    float2 b = *(const float2*)(bias + 2 * lane);

    float d_skq = s.x * (k.x + q.x) + s.y * (k.y + q.y);
    float d_sq  = s.x * q.x + s.y * q.y;
    float d_nk  = n.x * k.x + n.y * k.y;
#pragma unroll
    for (int o = 16; o; o >>= 1) {
        d_skq += __shfl_xor_sync(0xffffffffu, d_skq, o);
        d_sq  += __shfl_xor_sync(0xffffffffu, d_sq,  o);
        d_nk  += __shfl_xor_sync(0xffffffffu, d_nk,  o);
    }
    float e0v = d_skq;
    float e1v = d_nk + d_sq;
    e0v = (e0v > 0.f) ? e0v : expm1f(e0v);   // elu
    e1v = (e1v > 0.f) ? e1v : expm1f(e1v);
    float m = fmaxf(e0v, e1v);
    float a0 = expf(e0v - m), a1 = expf(e1v - m);
    float inv = 1.f / (a0 + a1);
    a0 *= inv; a1 *= inv;

    float2 o2 = make_float2(fmaf(a0, s.x, fmaf(a1, n.x, b.x)),
                            fmaf(a0, s.y, fmaf(a1, n.y, b.y)));
    *(float2*)(out + base + 2 * lane) = o2;
    if (lane == 0) { att[(size_t)gw * 2] = a0; att[(size_t)gw * 2 + 1] = a1; }
}

// ---------------- fused dual-weight GEMM with packed f32x2 FMA ----------------
// Cs (self path) stored fp32; Cr (rel path) stored fp16 for the SpMM gather.
#define BM 64
#define BN 128
#define BK 16

union F2 { float2 f; unsigned long long u; };
union H8 { __half2 h[4]; uint4 u; };

__global__ __launch_bounds__(128) void gemm_dual_kernel(
    const float* __restrict__ X, const float* __restrict__ Ws, const float* __restrict__ Wr,
    float* __restrict__ Cs, __half* __restrict__ Cr, int nrows)
{
    __shared__ float As[BK][BM];        // transposed tile: As[k][m]
    __shared__ float Bs[BK][BN];

    const int tid = threadIdx.x;        // 0..127
    const int block_row = blockIdx.x * BM;
    const int rg = tid >> 4;            // 0..7  (row group of 8)
    const int cg = tid & 15;            // 0..15 (col group of 8)

    F2 acc[4][8];
#pragma unroll
    for (int i = 0; i < 4; i++)
#pragma unroll
        for (int j = 0; j < 8; j++) acc[i][j].u = 0ULL;

    for (int k0 = 0; k0 < DIN; k0 += BK) {
#pragma unroll
        for (int i = tid; i < BM * BK / 4; i += 128) {
            int m = i >> 2, kq = i & 3;
            int r = block_row + m;
            float4 v = make_float4(0.f, 0.f, 0.f, 0.f);
            if (r < nrows)
                v = *(const float4*)(X + (size_t)r * DIN + k0 + kq * 4);
            As[kq * 4 + 0][m] = v.x;
            As[kq * 4 + 1][m] = v.y;
            As[kq * 4 + 2][m] = v.z;
            As[kq * 4 + 3][m] = v.w;
        }
#pragma unroll
        for (int i = tid; i < BK * BN / 4; i += 128) {
            int k = i >> 5;
            int c4 = i & 31;
            float4 v;
            if (c4 < 16) v = *(const float4*)(Ws + (size_t)(k0 + k) * DOUT + c4 * 4);
            else         v = *(const float4*)(Wr + (size_t)(k0 + k) * DOUT + (c4 - 16) * 4);
            *(float4*)&Bs[k][c4 * 4] = v;
        }
        __syncthreads();

#pragma unroll
        for (int k = 0; k < BK; k++) {
            float4 a0 = *(const float4*)&As[k][rg * 8];
            float4 a1 = *(const float4*)&As[k][rg * 8 + 4];
            float4 b0 = *(const float4*)&Bs[k][cg * 8];
            float4 b1 = *(const float4*)&Bs[k][cg * 8 + 4];

            F2 ap[4];
            ap[0].f = make_float2(a0.x, a0.y);
            ap[1].f = make_float2(a0.z, a0.w);
            ap[2].f = make_float2(a1.x, a1.y);
            ap[3].f = make_float2(a1.z, a1.w);

            float bv[8] = {b0.x, b0.y, b0.z, b0.w, b1.x, b1.y, b1.z, b1.w};
#pragma unroll
            for (int j = 0; j < 8; j++) {
                F2 bd; bd.f = make_float2(bv[j], bv[j]);
#pragma unroll
                for (int ip = 0; ip < 4; ip++) {
                    asm("fma.rn.f32x2 %0, %1, %2, %3;"
                        : "=l"(acc[ip][j].u)
                        : "l"(ap[ip].u), "l"(bd.u), "l"(acc[ip][j].u));
                }
            }
        }
        __syncthreads();
    }

    const int cbase = cg * 8;
    if (cbase < 64) {
        const int ccol = cbase;
#pragma unroll
        for (int ip = 0; ip < 4; ip++) {
            int r0 = block_row + rg * 8 + 2 * ip;
            int r1 = r0 + 1;
            if (r0 < nrows) {
                *(float4*)(Cs + (size_t)r0 * DOUT + ccol) =
                    make_float4(acc[ip][0].f.x, acc[ip][1].f.x, acc[ip][2].f.x, acc[ip][3].f.x);
                *(float4*)(Cs + (size_t)r0 * DOUT + ccol + 4) =
                    make_float4(acc[ip][4].f.x, acc[ip][5].f.x, acc[ip][6].f.x, acc[ip][7].f.x);
            }
            if (r1 < nrows) {
                *(float4*)(Cs + (size_t)r1 * DOUT + ccol) =
                    make_float4(acc[ip][0].f.y, acc[ip][1].f.y, acc[ip][2].f.y, acc[ip][3].f.y);
                *(float4*)(Cs + (size_t)r1 * DOUT + ccol + 4) =
                    make_float4(acc[ip][4].f.y, acc[ip][5].f.y, acc[ip][6].f.y, acc[ip][7].f.y);
            }
        }
    } else {
        const int ccol = cbase - 64;
#pragma unroll
        for (int ip = 0; ip < 4; ip++) {
            int r0 = block_row + rg * 8 + 2 * ip;
            int r1 = r0 + 1;
            if (r0 < nrows) {
                H8 p;
                p.h[0] = __floats2half2_rn(acc[ip][0].f.x, acc[ip][1].f.x);
                p.h[1] = __floats2half2_rn(acc[ip][2].f.x, acc[ip][3].f.x);
                p.h[2] = __floats2half2_rn(acc[ip][4].f.x, acc[ip][5].f.x);
                p.h[3] = __floats2half2_rn(acc[ip][6].f.x, acc[ip][7].f.x);
                *(uint4*)(Cr + (size_t)r0 * DOUT + ccol) = p.u;
            }
            if (r1 < nrows) {
                H8 p;
                p.h[0] = __floats2half2_rn(acc[ip][0].f.y, acc[ip][1].f.y);
                p.h[1] = __floats2half2_rn(acc[ip][2].f.y, acc[ip][3].f.y);
                p.h[2] = __floats2half2_rn(acc[ip][4].f.y, acc[ip][5].f.y);
                p.h[3] = __floats2half2_rn(acc[ip][6].f.y, acc[ip][7].f.y);
                *(uint4*)(Cr + (size_t)r1 * DOUT + ccol) = p.u;
            }
        }
    }
}

// ---------------- launch ----------------
extern "C" void kernel_launch(void* const* d_in, const int* in_sizes, int n_in,
                              void* d_out, int out_size) {
    const float* x_p       = (const float*)d_in[0];
    const float* x_a       = (const float*)d_in[1];
    const int*   adj_a_row = (const int*)d_in[2];
    const int*   adj_a_col = (const int*)d_in[3];
    const float* adj_a_val = (const float*)d_in[4];
    const int*   adj_p_row = (const int*)d_in[5];
    const int*   adj_p_col = (const int*)d_in[6];
    const float* adj_p_val = (const float*)d_in[7];
    const float* w_self_p  = (const float*)d_in[8];
    const float* w_rel_p_a = (const float*)d_in[9];
    const float* bias_p    = (const float*)d_in[10];
    const float* w_query_p = (const float*)d_in[11];
    const float* w_keys_p  = (const float*)d_in[12];
    const float* w_att_p   = (const float*)d_in[13];
    const float* w_self_a  = (const float*)d_in[14];
    const float* w_rel_a_p = (const float*)d_in[15];
    const float* bias_a    = (const float*)d_in[16];
    const float* w_query_a = (const float*)d_in[17];
    const float* w_keys_a  = (const float*)d_in[18];
    const float* w_att_a   = (const float*)d_in[19];

    float* out = (float*)d_out;
    float* out_p = out;
    float* out_a = out + (size_t)NNODES * DOUT;
    float* att_p = out + (size_t)2 * NNODES * DOUT;
    float* att_a = att_p + (size_t)NNODES * 2;

    float *p_self_p, *p_self_a, *p_nb_p, *p_nb_a, *p_vkq;
    __half2 *p_rels_p, *p_rels_a;
    int *p_cnt, *p_off, *p_cur, *p_bsum;
    int2 *p_edge;
    cudaGetSymbolAddress((void**)&p_self_p, g_self_p);
    cudaGetSymbolAddress((void**)&p_self_a, g_self_a);
    cudaGetSymbolAddress((void**)&p_rels_p, g_rels_p);
    cudaGetSymbolAddress((void**)&p_rels_a, g_rels_a);
    cudaGetSymbolAddress((void**)&p_nb_p, g_nb_p);
    cudaGetSymbolAddress((void**)&p_nb_a, g_nb_a);
    cudaGetSymbolAddress((void**)&p_vkq, g_vkq);
    cudaGetSymbolAddress((void**)&p_cnt, g_cnt);
    cudaGetSymbolAddress((void**)&p_off, g_off);
    cudaGetSymbolAddress((void**)&p_cur, g_cur);
    cudaGetSymbolAddress((void**)&p_bsum, g_bsum);
    cudaGetSymbolAddress((void**)&p_edge, g_edge);

    static cudaStream_t s1 = nullptr;
    static cudaEvent_t e_fork = nullptr, e_build = nullptr, e_ga = nullptr,
                       e_gp = nullptr, e_sp = nullptr;
    if (s1 == nullptr) {
        cudaStreamCreateWithFlags(&s1, cudaStreamNonBlocking);
        cudaEventCreateWithFlags(&e_fork, cudaEventDisableTiming);
        cudaEventCreateWithFlags(&e_build, cudaEventDisableTiming);
        cudaEventCreateWithFlags(&e_ga, cudaEventDisableTiming);
        cudaEventCreateWithFlags(&e_gp, cudaEventDisableTiming);
        cudaEventCreateWithFlags(&e_sp, cudaEventDisableTiming);
    }

    const int EB = (NEDGE + 255) / 256;
    const int NBK = (NNODES + 255) / 256;
    const int gblocks = (NNODES + BM - 1) / BM;
    const int wblocks = (NNODES * 32 + 255) / 256;   // warp-per-node kernels

    // fork
    cudaEventRecord(e_fork, 0);
    cudaStreamWaitEvent(s1, e_fork, 0);

    // ---- s1: attention fold + CSR build for both relations ----
    vkq_kernel<<<1, 256, 0, s1>>>(w_keys_p, w_query_p, w_att_p, w_keys_a, w_query_a, w_att_a);
    zero_cnt_kernel<<<(2 * NNODES + 255) / 256, 256, 0, s1>>>();
    hist_kernel<<<EB, 256, 0, s1>>>(adj_a_row, p_cnt);
    hist_kernel<<<EB, 256, 0, s1>>>(adj_p_row, p_cnt + NNODES);
    for (int rel = 0; rel < 2; rel++) {
        scan1_kernel<<<NB, SCAN_BLK, 0, s1>>>(p_cnt + rel * NNODES, p_off + rel * NNODES,
                                              p_bsum + rel * (NB + 1));
        scan2_kernel<<<1, 128, 0, s1>>>(p_bsum + rel * (NB + 1));
        scan3_kernel<<<NBK, 256, 0, s1>>>(p_off + rel * NNODES, p_cur + rel * NNODES,
                                          p_bsum + rel * (NB + 1));
    }
    scatter_kernel<<<EB, 256, 0, s1>>>(adj_a_row, adj_a_col, adj_a_val, p_cur, p_edge);
    scatter_kernel<<<EB, 256, 0, s1>>>(adj_p_row, adj_p_col, adj_p_val, p_cur + NNODES,
                                       p_edge + NEDGE);
    cudaEventRecord(e_build, s1);

    // ---- s0: GEMM_a (produces self_a, rels_a) then GEMM_p ----
    gemm_dual_kernel<<<gblocks, 128>>>(x_a, w_self_a, w_rel_p_a, p_self_a, (__half*)p_rels_a,
                                       NNODES);
    cudaEventRecord(e_ga, 0);
    gemm_dual_kernel<<<gblocks, 128>>>(x_p, w_self_p, w_rel_a_p, p_self_p, (__half*)p_rels_p,
                                       NNODES);
    cudaEventRecord(e_gp, 0);

    // ---- s1: spmm_p (needs build + rels_a) — overlaps GEMM_p on s0 ----
    cudaStreamWaitEvent(s1, e_ga, 0);
    spmm_nb_kernel<<<wblocks, 256, 0, s1>>>(p_off, p_cnt, p_edge, p_rels_a, p_nb_p);
    cudaStreamWaitEvent(s1, e_gp, 0);
    finalize_kernel<<<wblocks, 256, 0, s1>>>(p_self_p, p_nb_p, bias_p,
                                             p_vkq + 0 * DOUT, p_vkq + 1 * DOUT, out_p, att_p);
    cudaEventRecord(e_sp, s1);

    // ---- s0: spmm_a (needs build + rels_p) + finalize_a ----
    cudaStreamWaitEvent(0, e_build, 0);
    spmm_nb_kernel<<<wblocks, 256>>>(p_off + NNODES, p_cnt + NNODES, p_edge + NEDGE,
                                     p_rels_p, p_nb_a);
    finalize_kernel<<<wblocks, 256>>>(p_self_a, p_nb_a, bias_a,
                                      p_vkq + 2 * DOUT, p_vkq + 3 * DOUT, out_a, att_a);

    // join s1 back into origin stream
    cudaStreamWaitEvent(0, e_sp, 0);
}

// round 7
// speedup vs baseline: 1.7319x; 1.2851x over previous
#include <cuda_runtime.h>
#include <cuda_fp16.h>
#include <math.h>

#define NNODES 100000
#define DIN 256
#define DOUT 64
#define NEDGE 3200000
#define SCAN_BLK 1024
#define NB ((NNODES + SCAN_BLK - 1) / SCAN_BLK)   // 98

// ---------------- scratch (device globals; no allocation allowed) ----------------
__device__ float   g_self_p[NNODES * DOUT];    // x_p @ w_self_p   (fp32)
__device__ float   g_self_a[NNODES * DOUT];    // x_a @ w_self_a
__device__ __half2 g_rels_p[NNODES * DOUT/2];  // x_p @ w_rel_a_p  (fp16 gather table)
__device__ __half2 g_rels_a[NNODES * DOUT/2];  // x_a @ w_rel_p_a
__device__ float   g_nb_p[NNODES * DOUT];      // aggregated neighbor feats (interleaved)
__device__ float   g_nb_a[NNODES * DOUT];
__device__ float   g_vkq[4 * DOUT];

// CSR build scratch (2 relations)
__device__ int  g_cnt[2][NNODES];
__device__ int  g_off[2][NNODES];
__device__ int  g_cur[2][NNODES];
__device__ int  g_bsum[2][NB + 1];
__device__ int2 g_edge[2][NEDGE];              // packed {col, val-bits}

// ---------------- fold attention projections into 64-vectors ----------------
__global__ void vkq_kernel(const float* __restrict__ wk_p, const float* __restrict__ wq_p,
                           const float* __restrict__ wa_p,
                           const float* __restrict__ wk_a, const float* __restrict__ wq_a,
                           const float* __restrict__ wa_a) {
    int t = threadIdx.x;
    if (t >= 4 * DOUT) return;
    int which = t >> 6, d = t & 63;
    const float* W; const float* a;
    if (which == 0)      { W = wk_p; a = wa_p; }
    else if (which == 1) { W = wq_p; a = wa_p + DOUT; }
    else if (which == 2) { W = wk_a; a = wa_a; }
    else                 { W = wq_a; a = wa_a + DOUT; }
    float s = 0.f;
#pragma unroll 16
    for (int i = 0; i < DOUT; i++) s += W[d * DOUT + i] * a[i];
    g_vkq[which * DOUT + d] = s;
}

// ---------------- CSR build ----------------
__global__ void zero_cnt_kernel() {
    int i = blockIdx.x * blockDim.x + threadIdx.x;
    if (i < 2 * NNODES) ((int*)g_cnt)[i] = 0;
}

// both relations in one launch
__global__ void hist2_kernel(const int* __restrict__ rowa, const int* __restrict__ rowp) {
    int e = blockIdx.x * blockDim.x + threadIdx.x;
    if (e < NEDGE)               atomicAdd(&g_cnt[0][__ldg(rowa + e)], 1);
    else if (e < 2 * NEDGE)      atomicAdd(&g_cnt[1][__ldg(rowp + e - NEDGE)], 1);
}

__global__ void scan1_kernel(const int* __restrict__ cnt, int* __restrict__ off,
                             int* __restrict__ bsum) {
    __shared__ int s[SCAN_BLK];
    int t = threadIdx.x;
    int i = blockIdx.x * SCAN_BLK + t;
    int v = (i < NNODES) ? cnt[i] : 0;
    s[t] = v;
    __syncthreads();
#pragma unroll
    for (int o = 1; o < SCAN_BLK; o <<= 1) {
        int x = (t >= o) ? s[t - o] : 0;
        __syncthreads();
        s[t] += x;
        __syncthreads();
    }
    if (i < NNODES) off[i] = s[t] - v;      // exclusive within block
    if (t == SCAN_BLK - 1) bsum[blockIdx.x] = s[t];
}

__global__ void scan2_kernel(int* __restrict__ bsum) {
    __shared__ int s[128];
    int t = threadIdx.x;
    int v = (t < NB) ? bsum[t] : 0;
    s[t] = v;
    __syncthreads();
#pragma unroll
    for (int o = 1; o < 128; o <<= 1) {
        int x = (t >= o) ? s[t - o] : 0;
        __syncthreads();
        s[t] += x;
        __syncthreads();
    }
    if (t < NB) bsum[t] = s[t] - v;          // exclusive
}

__global__ void scan3_kernel(int* __restrict__ off, int* __restrict__ cur,
                             const int* __restrict__ bsum) {
    int i = blockIdx.x * blockDim.x + threadIdx.x;
    if (i < NNODES) {
        int o = off[i] + bsum[i >> 10];
        off[i] = o;
        cur[i] = o;
    }
}

// both relations in one launch
__global__ void scatter2_kernel(const int* __restrict__ rowa, const int* __restrict__ cola,
                                const float* __restrict__ vala,
                                const int* __restrict__ rowp, const int* __restrict__ colp,
                                const float* __restrict__ valp) {
    int e = blockIdx.x * blockDim.x + threadIdx.x;
    if (e < NEDGE) {
        int r = __ldg(rowa + e);
        int pos = atomicAdd(&g_cur[0][r], 1);
        g_edge[0][pos] = make_int2(__ldg(cola + e), __float_as_int(__ldg(vala + e)));
    } else if (e < 2 * NEDGE) {
        int i = e - NEDGE;
        int r = __ldg(rowp + i);
        int pos = atomicAdd(&g_cur[1][r], 1);
        g_edge[1][pos] = make_int2(__ldg(colp + i), __float_as_int(__ldg(valp + i)));
    }
}

// ---------------- combined gather SpMM (R4 body): warp per dst node, both rels ------
__global__ __launch_bounds__(256) void spmm2_kernel() {
    int gw = (blockIdx.x * blockDim.x + threadIdx.x) >> 5;
    int lane = threadIdx.x & 31;
    if (gw >= 2 * NNODES) return;
    int rel = (gw >= NNODES) ? 1 : 0;
    int node = gw - rel * NNODES;

    const int*  off   = g_off[rel];
    const int*  cnt   = g_cnt[rel];
    const int2* edges = g_edge[rel];
    const __half2* src = rel ? g_rels_p : g_rels_a;   // rel0 (adj_a) gathers x_a@w_rel_p_a
    float* nb          = rel ? g_nb_a   : g_nb_p;

    int start = __ldg(off + node);
    int deg   = __ldg(cnt + node);

    float a0 = 0.f, a1 = 0.f;
    int i = 0;
    for (; i + 4 <= deg; i += 4) {
        int2 e0 = __ldg(edges + start + i);
        int2 e1 = __ldg(edges + start + i + 1);
        int2 e2 = __ldg(edges + start + i + 2);
        int2 e3 = __ldg(edges + start + i + 3);
        __half2 h0 = __ldg(src + (size_t)e0.x * 32 + lane);
        __half2 h1 = __ldg(src + (size_t)e1.x * 32 + lane);
        __half2 h2 = __ldg(src + (size_t)e2.x * 32 + lane);
        __half2 h3 = __ldg(src + (size_t)e3.x * 32 + lane);
        float v0 = __int_as_float(e0.y), v1 = __int_as_float(e1.y);
        float v2 = __int_as_float(e2.y), v3 = __int_as_float(e3.y);
        float2 f0 = __half22float2(h0), f1 = __half22float2(h1);
        float2 f2 = __half22float2(h2), f3 = __half22float2(h3);
        a0 = fmaf(v0, f0.x, a0); a1 = fmaf(v0, f0.y, a1);
        a0 = fmaf(v1, f1.x, a0); a1 = fmaf(v1, f1.y, a1);
        a0 = fmaf(v2, f2.x, a0); a1 = fmaf(v2, f2.y, a1);
        a0 = fmaf(v3, f3.x, a0); a1 = fmaf(v3, f3.y, a1);
    }
    for (; i < deg; i++) {
        int2 e0 = __ldg(edges + start + i);
        __half2 h0 = __ldg(src + (size_t)e0.x * 32 + lane);
        float v0 = __int_as_float(e0.y);
        float2 f0 = __half22float2(h0);
        a0 = fmaf(v0, f0.x, a0); a1 = fmaf(v0, f0.y, a1);
    }
    *(float2*)(nb + (size_t)node * DOUT + 2 * lane) = make_float2(a0, a1);
}

// ---------------- combined attention mix + output, warp per node --------------------
__global__ __launch_bounds__(256) void finalize2_kernel(
    const float* __restrict__ bias_p, const float* __restrict__ bias_a,
    float* __restrict__ out_p, float* __restrict__ out_a,
    float* __restrict__ att_p, float* __restrict__ att_a)
{
    int gw = (blockIdx.x * blockDim.x + threadIdx.x) >> 5;
    int lane = threadIdx.x & 31;
    if (gw >= 2 * NNODES) return;
    int typ = (gw >= NNODES) ? 1 : 0;           // 0 = p, 1 = a
    int node = gw - typ * NNODES;

    const float* selfft = typ ? g_self_a : g_self_p;
    const float* nbft   = typ ? g_nb_a   : g_nb_p;
    const float* bias   = typ ? bias_a   : bias_p;
    const float* vk     = g_vkq + (typ ? 2 : 0) * DOUT;
    const float* vq     = g_vkq + (typ ? 3 : 1) * DOUT;
    float* out          = typ ? out_a : out_p;
    float* att          = typ ? att_a : att_p;

    size_t base = (size_t)node * DOUT;
    float2 s = *(const float2*)(selfft + base + 2 * lane);
    float2 n = *(const float2*)(nbft + base + 2 * lane);
    float2 k = *(const float2*)(vk + 2 * lane);
    float2 q = *(const float2*)(vq + 2 * lane);
    float2 b = *(const float2*)(bias + 2 * lane);

    float d_skq = s.x * (k.x + q.x) + s.y * (k.y + q.y);
    float d_sq  = s.x * q.x + s.y * q.y;
    float d_nk  = n.x * k.x + n.y * k.y;
#pragma unroll
    for (int o = 16; o; o >>= 1) {
        d_skq += __shfl_xor_sync(0xffffffffu, d_skq, o);
        d_sq  += __shfl_xor_sync(0xffffffffu, d_sq,  o);
        d_nk  += __shfl_xor_sync(0xffffffffu, d_nk,  o);
    }
    float e0v = d_skq;
    float e1v = d_nk + d_sq;
    e0v = (e0v > 0.f) ? e0v : expm1f(e0v);   // elu
    e1v = (e1v > 0.f) ? e1v : expm1f(e1v);
    float m = fmaxf(e0v, e1v);
    float a0 = expf(e0v - m), a1 = expf(e1v - m);
    float inv = 1.f / (a0 + a1);
    a0 *= inv; a1 *= inv;

    float2 o2 = make_float2(fmaf(a0, s.x, fmaf(a1, n.x, b.x)),
                            fmaf(a0, s.y, fmaf(a1, n.y, b.y)));
    *(float2*)(out + base + 2 * lane) = o2;
    if (lane == 0) { att[(size_t)node * 2] = a0; att[(size_t)node * 2 + 1] = a1; }
}

// ---------------- tf32 tensor-core dual GEMM ----------------
// C[:, :64] = X@Ws (fp32 out), C[:, 64:] = X@Wr (fp16 out).
// Block tile 128x128x32, 8 warps (2x4), warp tile 64x32, mma.m16n8k8 tf32.
#define GBM 128
#define GBK 32

__device__ __forceinline__ unsigned f2tf32(float f) {
    unsigned u;
    asm("cvt.rna.tf32.f32 %0, %1;" : "=r"(u) : "f"(f));
    return u;
}

__global__ __launch_bounds__(256, 1) void gemm_tf32_kernel(
    const float* __restrict__ X, const float* __restrict__ Ws, const float* __restrict__ Wr,
    float* __restrict__ Cs, __half* __restrict__ Cr, int nrows)
{
    __shared__ unsigned As[GBM][36];    // pad 36: bank = 4m+k mod 32, conflict-free frags
    __shared__ unsigned Bs[GBK][136];   // pad 136: bank = 8k+n mod 32, conflict-free frags

    const int tid = threadIdx.x;
    const int wid = tid >> 5, lane = tid & 31;
    const int g = lane >> 2, t4 = lane & 3;
    const int wr = wid >> 2, wc = wid & 3;          // warp grid 2x4
    const int mwarp = wr * 64, nwarp = wc * 32;
    const int rowbase = blockIdx.x * GBM;

    float c[4][4][4];
#pragma unroll
    for (int mi = 0; mi < 4; mi++)
#pragma unroll
        for (int nj = 0; nj < 4; nj++)
#pragma unroll
            for (int u = 0; u < 4; u++) c[mi][nj][u] = 0.f;

    for (int k0 = 0; k0 < DIN; k0 += GBK) {
        // X tile: 128 rows x 32 k (1024 float4; 4 per thread), clamp OOB rows
#pragma unroll
        for (int j = 0; j < 4; j++) {
            int i = tid + 256 * j;
            int r = i >> 3, qq = i & 7;
            int gr = min(rowbase + r, NNODES - 1);
            float4 v = *(const float4*)(X + (size_t)gr * DIN + k0 + qq * 4);
            uint4 u = make_uint4(f2tf32(v.x), f2tf32(v.y), f2tf32(v.z), f2tf32(v.w));
            *(uint4*)&As[r][qq * 4] = u;
        }
        // W tile: 32 k x 128 n (first 64 Ws, next 64 Wr)
#pragma unroll
        for (int j = 0; j < 4; j++) {
            int i = tid + 256 * j;
            int k = i >> 5, qq = i & 31;
            int n0 = qq * 4;
            const float* Wp = (n0 < 64) ? (Ws + (size_t)(k0 + k) * DOUT + n0)
                                        : (Wr + (size_t)(k0 + k) * DOUT + (n0 - 64));
            float4 v = *(const float4*)Wp;
            uint4 u = make_uint4(f2tf32(v.x), f2tf32(v.y), f2tf32(v.z), f2tf32(v.w));
            *(uint4*)&Bs[k][n0] = u;
        }
        __syncthreads();

#pragma unroll
        for (int k8 = 0; k8 < 4; k8++) {
            const int kk = k8 * 8;
            unsigned af[4][4];
#pragma unroll
            for (int mi = 0; mi < 4; mi++) {
                int mrow = mwarp + mi * 16;
                af[mi][0] = As[mrow + g][kk + t4];
                af[mi][1] = As[mrow + g + 8][kk + t4];
                af[mi][2] = As[mrow + g][kk + t4 + 4];
                af[mi][3] = As[mrow + g + 8][kk + t4 + 4];
            }
            unsigned bf[4][2];
#pragma unroll
            for (int nj = 0; nj < 4; nj++) {
                int ncol = nwarp + nj * 8 + g;
                bf[nj][0] = Bs[kk + t4][ncol];
                bf[nj][1] = Bs[kk + t4 + 4][ncol];
            }
#pragma unroll
            for (int mi = 0; mi < 4; mi++)
#pragma unroll
                for (int nj = 0; nj < 4; nj++) {
                    asm volatile(
                        "mma.sync.aligned.m16n8k8.row.col.f32.tf32.tf32.f32 "
                        "{%0,%1,%2,%3}, {%4,%5,%6,%7}, {%8,%9}, {%0,%1,%2,%3};"
                        : "+f"(c[mi][nj][0]), "+f"(c[mi][nj][1]),
                          "+f"(c[mi][nj][2]), "+f"(c[mi][nj][3])
                        : "r"(af[mi][0]), "r"(af[mi][1]), "r"(af[mi][2]), "r"(af[mi][3]),
                          "r"(bf[nj][0]), "r"(bf[nj][1]));
                }
        }
        __syncthreads();
    }

    // epilogue: c0,c1 -> (row, 2t4), (row, 2t4+1); c2,c3 -> row+8
#pragma unroll
    for (int mi = 0; mi < 4; mi++) {
        int row0 = rowbase + mwarp + mi * 16 + g;
        int row1 = row0 + 8;
#pragma unroll
        for (int nj = 0; nj < 4; nj++) {
            int n = nwarp + nj * 8 + 2 * t4;
            if (wc < 2) {          // self path -> fp32
                if (row0 < nrows)
                    *(float2*)(Cs + (size_t)row0 * DOUT + n) =
                        make_float2(c[mi][nj][0], c[mi][nj][1]);
                if (row1 < nrows)
                    *(float2*)(Cs + (size_t)row1 * DOUT + n) =
                        make_float2(c[mi][nj][2], c[mi][nj][3]);
            } else {               // rel path -> fp16
                int nn = n - 64;
                if (row0 < nrows)
                    *(__half2*)(Cr + (size_t)row0 * DOUT + nn) =
                        __floats2half2_rn(c[mi][nj][0], c[mi][nj][1]);
                if (row1 < nrows)
                    *(__half2*)(Cr + (size_t)row1 * DOUT + nn) =
                        __floats2half2_rn(c[mi][nj][2], c[mi][nj][3]);
            }
        }
    }
}

// ---------------- launch ----------------
extern "C" void kernel_launch(void* const* d_in, const int* in_sizes, int n_in,
                              void* d_out, int out_size) {
    const float* x_p       = (const float*)d_in[0];
    const float* x_a       = (const float*)d_in[1];
    const int*   adj_a_row = (const int*)d_in[2];
    const int*   adj_a_col = (const int*)d_in[3];
    const float* adj_a_val = (const float*)d_in[4];
    const int*   adj_p_row = (const int*)d_in[5];
    const int*   adj_p_col = (const int*)d_in[6];
    const float* adj_p_val = (const float*)d_in[7];
    const float* w_self_p  = (const float*)d_in[8];
    const float* w_rel_p_a = (const float*)d_in[9];
    const float* bias_p    = (const float*)d_in[10];
    const float* w_query_p = (const float*)d_in[11];
    const float* w_keys_p  = (const float*)d_in[12];
    const float* w_att_p   = (const float*)d_in[13];
    const float* w_self_a  = (const float*)d_in[14];
    const float* w_rel_a_p = (const float*)d_in[15];
    const float* bias_a    = (const float*)d_in[16];
    const float* w_query_a = (const float*)d_in[17];
    const float* w_keys_a  = (const float*)d_in[18];
    const float* w_att_a   = (const float*)d_in[19];

    float* out = (float*)d_out;
    float* out_p = out;
    float* out_a = out + (size_t)NNODES * DOUT;
    float* att_p = out + (size_t)2 * NNODES * DOUT;
    float* att_a = att_p + (size_t)NNODES * 2;

    float *p_self_p, *p_self_a;
    __half2 *p_rels_p, *p_rels_a;
    int *p_cnt, *p_off, *p_cur, *p_bsum;
    cudaGetSymbolAddress((void**)&p_self_p, g_self_p);
    cudaGetSymbolAddress((void**)&p_self_a, g_self_a);
    cudaGetSymbolAddress((void**)&p_rels_p, g_rels_p);
    cudaGetSymbolAddress((void**)&p_rels_a, g_rels_a);
    cudaGetSymbolAddress((void**)&p_cnt, g_cnt);
    cudaGetSymbolAddress((void**)&p_off, g_off);
    cudaGetSymbolAddress((void**)&p_cur, g_cur);
    cudaGetSymbolAddress((void**)&p_bsum, g_bsum);

    static cudaStream_t s1 = nullptr;
    static cudaEvent_t e_fork = nullptr, e_build = nullptr;
    if (s1 == nullptr) {
        cudaStreamCreateWithFlags(&s1, cudaStreamNonBlocking);
        cudaEventCreateWithFlags(&e_fork, cudaEventDisableTiming);
        cudaEventCreateWithFlags(&e_build, cudaEventDisableTiming);
    }

    const int EB2 = (2 * NEDGE + 255) / 256;
    const int NBK = (NNODES + 255) / 256;
    const int gblocks = (NNODES + GBM - 1) / GBM;
    const int wblocks2 = (2 * NNODES * 32 + 255) / 256;   // combined warp-per-node

    // fork
    cudaEventRecord(e_fork, 0);
    cudaStreamWaitEvent(s1, e_fork, 0);

    // ---- s1: attention fold + CSR build (both relations, merged launches) ----
    vkq_kernel<<<1, 256, 0, s1>>>(w_keys_p, w_query_p, w_att_p, w_keys_a, w_query_a, w_att_a);
    zero_cnt_kernel<<<(2 * NNODES + 255) / 256, 256, 0, s1>>>();
    hist2_kernel<<<EB2, 256, 0, s1>>>(adj_a_row, adj_p_row);
    for (int rel = 0; rel < 2; rel++) {
        scan1_kernel<<<NB, SCAN_BLK, 0, s1>>>(p_cnt + rel * NNODES, p_off + rel * NNODES,
                                              p_bsum + rel * (NB + 1));
        scan2_kernel<<<1, 128, 0, s1>>>(p_bsum + rel * (NB + 1));
        scan3_kernel<<<NBK, 256, 0, s1>>>(p_off + rel * NNODES, p_cur + rel * NNODES,
                                          p_bsum + rel * (NB + 1));
    }
    scatter2_kernel<<<EB2, 256, 0, s1>>>(adj_a_row, adj_a_col, adj_a_val,
                                         adj_p_row, adj_p_col, adj_p_val);
    cudaEventRecord(e_build, s1);

    // ---- s0: tf32 GEMMs (short chain) ----
    gemm_tf32_kernel<<<gblocks, 256>>>(x_a, w_self_a, w_rel_p_a, p_self_a, (__half*)p_rels_a,
                                       NNODES);
    gemm_tf32_kernel<<<gblocks, 256>>>(x_p, w_self_p, w_rel_a_p, p_self_p, (__half*)p_rels_p,
                                       NNODES);

    // ---- s0: join build, then both SpMMs in ONE launch (forced overlap), finalize ----
    cudaStreamWaitEvent(0, e_build, 0);
    spmm2_kernel<<<wblocks2, 256>>>();
    finalize2_kernel<<<wblocks2, 256>>>(bias_p, bias_a, out_p, out_a, att_p, att_a);
}

// round 8
// speedup vs baseline: 1.7861x; 1.0313x over previous
#include <cuda_runtime.h>
#include <cuda_fp16.h>
#include <math.h>

#define NNODES 100000
#define DIN 256
#define DOUT 64
#define NEDGE 3200000
#define SCAN_BLK 1024
#define NB ((NNODES + SCAN_BLK - 1) / SCAN_BLK)   // 98

// ---------------- scratch (device globals; no allocation allowed) ----------------
__device__ float   g_self_p[NNODES * DOUT];    // x_p @ w_self_p   (fp32)
__device__ float   g_self_a[NNODES * DOUT];    // x_a @ w_self_a
__device__ __half2 g_rels_p[NNODES * DOUT/2];  // x_p @ w_rel_a_p  (fp16 gather table)
__device__ __half2 g_rels_a[NNODES * DOUT/2];  // x_a @ w_rel_p_a
__device__ float   g_vkq[4 * DOUT];

// CSR build scratch (2 relations)
__device__ int  g_cnt[2][NNODES];
__device__ int  g_off[2][NNODES];
__device__ int  g_cur[2][NNODES];
__device__ int  g_bsum[2][NB + 1];
__device__ int2 g_edge[2][NEDGE];              // packed {col, val-bits}

// ---------------- fold attention projections into 64-vectors ----------------
__global__ void vkq_kernel(const float* __restrict__ wk_p, const float* __restrict__ wq_p,
                           const float* __restrict__ wa_p,
                           const float* __restrict__ wk_a, const float* __restrict__ wq_a,
                           const float* __restrict__ wa_a) {
    int t = threadIdx.x;
    if (t >= 4 * DOUT) return;
    int which = t >> 6, d = t & 63;
    const float* W; const float* a;
    if (which == 0)      { W = wk_p; a = wa_p; }
    else if (which == 1) { W = wq_p; a = wa_p + DOUT; }
    else if (which == 2) { W = wk_a; a = wa_a; }
    else                 { W = wq_a; a = wa_a + DOUT; }
    float s = 0.f;
#pragma unroll 16
    for (int i = 0; i < DOUT; i++) s += W[d * DOUT + i] * a[i];
    g_vkq[which * DOUT + d] = s;
}

// ---------------- CSR build ----------------
__global__ void zero_cnt_kernel() {
    int i = blockIdx.x * blockDim.x + threadIdx.x;
    if (i < 2 * NNODES) ((int*)g_cnt)[i] = 0;
}

__global__ void hist2_kernel(const int* __restrict__ rowa, const int* __restrict__ rowp) {
    int e = blockIdx.x * blockDim.x + threadIdx.x;
    if (e < NEDGE)               atomicAdd(&g_cnt[0][__ldg(rowa + e)], 1);
    else if (e < 2 * NEDGE)      atomicAdd(&g_cnt[1][__ldg(rowp + e - NEDGE)], 1);
}

__global__ void scan1_kernel(const int* __restrict__ cnt, int* __restrict__ off,
                             int* __restrict__ bsum) {
    __shared__ int s[SCAN_BLK];
    int t = threadIdx.x;
    int i = blockIdx.x * SCAN_BLK + t;
    int v = (i < NNODES) ? cnt[i] : 0;
    s[t] = v;
    __syncthreads();
#pragma unroll
    for (int o = 1; o < SCAN_BLK; o <<= 1) {
        int x = (t >= o) ? s[t - o] : 0;
        __syncthreads();
        s[t] += x;
        __syncthreads();
    }
    if (i < NNODES) off[i] = s[t] - v;      // exclusive within block
    if (t == SCAN_BLK - 1) bsum[blockIdx.x] = s[t];
}

__global__ void scan2_kernel(int* __restrict__ bsum) {
    __shared__ int s[128];
    int t = threadIdx.x;
    int v = (t < NB) ? bsum[t] : 0;
    s[t] = v;
    __syncthreads();
#pragma unroll
    for (int o = 1; o < 128; o <<= 1) {
        int x = (t >= o) ? s[t - o] : 0;
        __syncthreads();
        s[t] += x;
        __syncthreads();
    }
    if (t < NB) bsum[t] = s[t] - v;          // exclusive
}

__global__ void scan3_kernel(int* __restrict__ off, int* __restrict__ cur,
                             const int* __restrict__ bsum) {
    int i = blockIdx.x * blockDim.x + threadIdx.x;
    if (i < NNODES) {
        int o = off[i] + bsum[i >> 10];
        off[i] = o;
        cur[i] = o;
    }
}

__global__ void scatter2_kernel(const int* __restrict__ rowa, const int* __restrict__ cola,
                                const float* __restrict__ vala,
                                const int* __restrict__ rowp, const int* __restrict__ colp,
                                const float* __restrict__ valp) {
    int e = blockIdx.x * blockDim.x + threadIdx.x;
    if (e < NEDGE) {
        int r = __ldg(rowa + e);
        int pos = atomicAdd(&g_cur[0][r], 1);
        g_edge[0][pos] = make_int2(__ldg(cola + e), __float_as_int(__ldg(vala + e)));
    } else if (e < 2 * NEDGE) {
        int i = e - NEDGE;
        int r = __ldg(rowp + i);
        int pos = atomicAdd(&g_cur[1][r], 1);
        g_edge[1][pos] = make_int2(__ldg(colp + i), __float_as_int(__ldg(valp + i)));
    }
}

// ------- fused SpMM + attention + output: warp per dst node, both rels/types --------
// 8-wide straight-line edge groups (R4 shape, doubled MLP), 4-wide step, scalar tail.
__global__ __launch_bounds__(256) void spmm_final2_kernel(
    const float* __restrict__ bias_p, const float* __restrict__ bias_a,
    float* __restrict__ out_p, float* __restrict__ out_a,
    float* __restrict__ att_p, float* __restrict__ att_a)
{
    int gw = (blockIdx.x * blockDim.x + threadIdx.x) >> 5;
    int lane = threadIdx.x & 31;
    if (gw >= 2 * NNODES) return;
    int rel = (gw >= NNODES) ? 1 : 0;           // rel0=adj_a->type p, rel1=adj_p->type a
    int node = gw - rel * NNODES;

    const int*     off   = g_off[rel];
    const int*     cnt   = g_cnt[rel];
    const int2*    edges = g_edge[rel];
    const __half2* src   = rel ? g_rels_p : g_rels_a;

    int start = __ldg(off + node);
    int deg   = __ldg(cnt + node);

    float a0 = 0.f, a1 = 0.f, b0 = 0.f, b1 = 0.f;
    int i = 0;
    for (; i + 8 <= deg; i += 8) {
        int2 e[8];
#pragma unroll
        for (int u = 0; u < 8; u++) e[u] = __ldg(edges + start + i + u);
        __half2 h[8];
#pragma unroll
        for (int u = 0; u < 8; u++) h[u] = __ldg(src + (size_t)e[u].x * 32 + lane);
#pragma unroll
        for (int u = 0; u < 8; u++) {
            float2 f = __half22float2(h[u]);
            float v = __int_as_float(e[u].y);
            if (u & 1) { b0 = fmaf(v, f.x, b0); b1 = fmaf(v, f.y, b1); }
            else       { a0 = fmaf(v, f.x, a0); a1 = fmaf(v, f.y, a1); }
        }
    }
    if (i + 4 <= deg) {
        int2 e[4];
#pragma unroll
        for (int u = 0; u < 4; u++) e[u] = __ldg(edges + start + i + u);
        __half2 h[4];
#pragma unroll
        for (int u = 0; u < 4; u++) h[u] = __ldg(src + (size_t)e[u].x * 32 + lane);
#pragma unroll
        for (int u = 0; u < 4; u++) {
            float2 f = __half22float2(h[u]);
            float v = __int_as_float(e[u].y);
            if (u & 1) { b0 = fmaf(v, f.x, b0); b1 = fmaf(v, f.y, b1); }
            else       { a0 = fmaf(v, f.x, a0); a1 = fmaf(v, f.y, a1); }
        }
        i += 4;
    }
    for (; i < deg; i++) {
        int2 e0 = __ldg(edges + start + i);
        __half2 h0 = __ldg(src + (size_t)e0.x * 32 + lane);
        float v0 = __int_as_float(e0.y);
        float2 f0 = __half22float2(h0);
        a0 = fmaf(v0, f0.x, a0); a1 = fmaf(v0, f0.y, a1);
    }
    float n0 = a0 + b0, n1 = a1 + b1;

    // ---- attention epilogue (reads self row, writes out + att directly) ----
    const float* selfft = rel ? g_self_a : g_self_p;
    const float* bias   = rel ? bias_a   : bias_p;
    const float* vk     = g_vkq + (rel ? 2 : 0) * DOUT;
    const float* vq     = g_vkq + (rel ? 3 : 1) * DOUT;
    float* out          = rel ? out_a : out_p;
    float* att          = rel ? att_a : att_p;

    size_t base = (size_t)node * DOUT;
    float2 s = *(const float2*)(selfft + base + 2 * lane);
    float2 k = *(const float2*)(vk + 2 * lane);
    float2 q = *(const float2*)(vq + 2 * lane);
    float2 b = *(const float2*)(bias + 2 * lane);

    float d_skq = s.x * (k.x + q.x) + s.y * (k.y + q.y);
    float d_sq  = s.x * q.x + s.y * q.y;
    float d_nk  = n0 * k.x + n1 * k.y;
#pragma unroll
    for (int o = 16; o; o >>= 1) {
        d_skq += __shfl_xor_sync(0xffffffffu, d_skq, o);
        d_sq  += __shfl_xor_sync(0xffffffffu, d_sq,  o);
        d_nk  += __shfl_xor_sync(0xffffffffu, d_nk,  o);
    }
    float e0v = d_skq;
    float e1v = d_nk + d_sq;
    e0v = (e0v > 0.f) ? e0v : expm1f(e0v);   // elu
    e1v = (e1v > 0.f) ? e1v : expm1f(e1v);
    float m = fmaxf(e0v, e1v);
    float w0 = expf(e0v - m), w1 = expf(e1v - m);
    float inv = 1.f / (w0 + w1);
    w0 *= inv; w1 *= inv;

    float2 o2 = make_float2(fmaf(w0, s.x, fmaf(w1, n0, b.x)),
                            fmaf(w0, s.y, fmaf(w1, n1, b.y)));
    *(float2*)(out + base + 2 * lane) = o2;
    if (lane == 0) { att[(size_t)node * 2] = w0; att[(size_t)node * 2 + 1] = w1; }
}

// ---------------- tf32 tensor-core dual GEMM ----------------
#define GBM 128
#define GBK 32

__device__ __forceinline__ unsigned f2tf32(float f) {
    unsigned u;
    asm("cvt.rna.tf32.f32 %0, %1;" : "=r"(u) : "f"(f));
    return u;
}

__global__ __launch_bounds__(256, 1) void gemm_tf32_kernel(
    const float* __restrict__ X, const float* __restrict__ Ws, const float* __restrict__ Wr,
    float* __restrict__ Cs, __half* __restrict__ Cr, int nrows)
{
    __shared__ unsigned As[GBM][36];
    __shared__ unsigned Bs[GBK][136];

    const int tid = threadIdx.x;
    const int wid = tid >> 5, lane = tid & 31;
    const int g = lane >> 2, t4 = lane & 3;
    const int wr = wid >> 2, wc = wid & 3;
    const int mwarp = wr * 64, nwarp = wc * 32;
    const int rowbase = blockIdx.x * GBM;

    float c[4][4][4];
#pragma unroll
    for (int mi = 0; mi < 4; mi++)
#pragma unroll
        for (int nj = 0; nj < 4; nj++)
#pragma unroll
            for (int u = 0; u < 4; u++) c[mi][nj][u] = 0.f;

    for (int k0 = 0; k0 < DIN; k0 += GBK) {
#pragma unroll
        for (int j = 0; j < 4; j++) {
            int i = tid + 256 * j;
            int r = i >> 3, qq = i & 7;
            int gr = min(rowbase + r, NNODES - 1);
            float4 v = *(const float4*)(X + (size_t)gr * DIN + k0 + qq * 4);
            uint4 u = make_uint4(f2tf32(v.x), f2tf32(v.y), f2tf32(v.z), f2tf32(v.w));
            *(uint4*)&As[r][qq * 4] = u;
        }
#pragma unroll
        for (int j = 0; j < 4; j++) {
            int i = tid + 256 * j;
            int k = i >> 5, qq = i & 31;
            int n0 = qq * 4;
            const float* Wp = (n0 < 64) ? (Ws + (size_t)(k0 + k) * DOUT + n0)
                                        : (Wr + (size_t)(k0 + k) * DOUT + (n0 - 64));
            float4 v = *(const float4*)Wp;
            uint4 u = make_uint4(f2tf32(v.x), f2tf32(v.y), f2tf32(v.z), f2tf32(v.w));
            *(uint4*)&Bs[k][n0] = u;
        }
        __syncthreads();

#pragma unroll
        for (int k8 = 0; k8 < 4; k8++) {
            const int kk = k8 * 8;
            unsigned af[4][4];
#pragma unroll
            for (int mi = 0; mi < 4; mi++) {
                int mrow = mwarp + mi * 16;
                af[mi][0] = As[mrow + g][kk + t4];
                af[mi][1] = As[mrow + g + 8][kk + t4];
                af[mi][2] = As[mrow + g][kk + t4 + 4];
                af[mi][3] = As[mrow + g + 8][kk + t4 + 4];
            }
            unsigned bf[4][2];
#pragma unroll
            for (int nj = 0; nj < 4; nj++) {
                int ncol = nwarp + nj * 8 + g;
                bf[nj][0] = Bs[kk + t4][ncol];
                bf[nj][1] = Bs[kk + t4 + 4][ncol];
            }
#pragma unroll
            for (int mi = 0; mi < 4; mi++)
#pragma unroll
                for (int nj = 0; nj < 4; nj++) {
                    asm volatile(
                        "mma.sync.aligned.m16n8k8.row.col.f32.tf32.tf32.f32 "
                        "{%0,%1,%2,%3}, {%4,%5,%6,%7}, {%8,%9}, {%0,%1,%2,%3};"
                        : "+f"(c[mi][nj][0]), "+f"(c[mi][nj][1]),
                          "+f"(c[mi][nj][2]), "+f"(c[mi][nj][3])
                        : "r"(af[mi][0]), "r"(af[mi][1]), "r"(af[mi][2]), "r"(af[mi][3]),
                          "r"(bf[nj][0]), "r"(bf[nj][1]));
                }
        }
        __syncthreads();
    }

#pragma unroll
    for (int mi = 0; mi < 4; mi++) {
        int row0 = rowbase + mwarp + mi * 16 + g;
        int row1 = row0 + 8;
#pragma unroll
        for (int nj = 0; nj < 4; nj++) {
            int n = nwarp + nj * 8 + 2 * t4;
            if (wc < 2) {
                if (row0 < nrows)
                    *(float2*)(Cs + (size_t)row0 * DOUT + n) =
                        make_float2(c[mi][nj][0], c[mi][nj][1]);
                if (row1 < nrows)
                    *(float2*)(Cs + (size_t)row1 * DOUT + n) =
                        make_float2(c[mi][nj][2], c[mi][nj][3]);
            } else {
                int nn = n - 64;
                if (row0 < nrows)
                    *(__half2*)(Cr + (size_t)row0 * DOUT + nn) =
                        __floats2half2_rn(c[mi][nj][0], c[mi][nj][1]);
                if (row1 < nrows)
                    *(__half2*)(Cr + (size_t)row1 * DOUT + nn) =
                        __floats2half2_rn(c[mi][nj][2], c[mi][nj][3]);
            }
        }
    }
}

// ---------------- launch ----------------
extern "C" void kernel_launch(void* const* d_in, const int* in_sizes, int n_in,
                              void* d_out, int out_size) {
    const float* x_p       = (const float*)d_in[0];
    const float* x_a       = (const float*)d_in[1];
    const int*   adj_a_row = (const int*)d_in[2];
    const int*   adj_a_col = (const int*)d_in[3];
    const float* adj_a_val = (const float*)d_in[4];
    const int*   adj_p_row = (const int*)d_in[5];
    const int*   adj_p_col = (const int*)d_in[6];
    const float* adj_p_val = (const float*)d_in[7];
    const float* w_self_p  = (const float*)d_in[8];
    const float* w_rel_p_a = (const float*)d_in[9];
    const float* bias_p    = (const float*)d_in[10];
    const float* w_query_p = (const float*)d_in[11];
    const float* w_keys_p  = (const float*)d_in[12];
    const float* w_att_p   = (const float*)d_in[13];
    const float* w_self_a  = (const float*)d_in[14];
    const float* w_rel_a_p = (const float*)d_in[15];
    const float* bias_a    = (const float*)d_in[16];
    const float* w_query_a = (const float*)d_in[17];
    const float* w_keys_a  = (const float*)d_in[18];
    const float* w_att_a   = (const float*)d_in[19];

    float* out = (float*)d_out;
    float* out_p = out;
    float* out_a = out + (size_t)NNODES * DOUT;
    float* att_p = out + (size_t)2 * NNODES * DOUT;
    float* att_a = att_p + (size_t)NNODES * 2;

    float *p_self_p, *p_self_a;
    __half2 *p_rels_p, *p_rels_a;
    int *p_cnt, *p_off, *p_cur, *p_bsum;
    cudaGetSymbolAddress((void**)&p_self_p, g_self_p);
    cudaGetSymbolAddress((void**)&p_self_a, g_self_a);
    cudaGetSymbolAddress((void**)&p_rels_p, g_rels_p);
    cudaGetSymbolAddress((void**)&p_rels_a, g_rels_a);
    cudaGetSymbolAddress((void**)&p_cnt, g_cnt);
    cudaGetSymbolAddress((void**)&p_off, g_off);
    cudaGetSymbolAddress((void**)&p_cur, g_cur);
    cudaGetSymbolAddress((void**)&p_bsum, g_bsum);

    static cudaStream_t s1 = nullptr;
    static cudaEvent_t e_fork = nullptr, e_build = nullptr;
    if (s1 == nullptr) {
        cudaStreamCreateWithFlags(&s1, cudaStreamNonBlocking);
        cudaEventCreateWithFlags(&e_fork, cudaEventDisableTiming);
        cudaEventCreateWithFlags(&e_build, cudaEventDisableTiming);
    }

    const int EB2 = (2 * NEDGE + 255) / 256;
    const int NBK = (NNODES + 255) / 256;
    const int gblocks = (NNODES + GBM - 1) / GBM;
    const int wblocks2 = (2 * NNODES * 32 + 255) / 256;

    // fork
    cudaEventRecord(e_fork, 0);
    cudaStreamWaitEvent(s1, e_fork, 0);

    // ---- s1: attention fold + CSR build (both relations, merged launches) ----
    vkq_kernel<<<1, 256, 0, s1>>>(w_keys_p, w_query_p, w_att_p, w_keys_a, w_query_a, w_att_a);
    zero_cnt_kernel<<<(2 * NNODES + 255) / 256, 256, 0, s1>>>();
    hist2_kernel<<<EB2, 256, 0, s1>>>(adj_a_row, adj_p_row);
    for (int rel = 0; rel < 2; rel++) {
        scan1_kernel<<<NB, SCAN_BLK, 0, s1>>>(p_cnt + rel * NNODES, p_off + rel * NNODES,
                                              p_bsum + rel * (NB + 1));
        scan2_kernel<<<1, 128, 0, s1>>>(p_bsum + rel * (NB + 1));
        scan3_kernel<<<NBK, 256, 0, s1>>>(p_off + rel * NNODES, p_cur + rel * NNODES,
                                          p_bsum + rel * (NB + 1));
    }
    scatter2_kernel<<<EB2, 256, 0, s1>>>(adj_a_row, adj_a_col, adj_a_val,
                                         adj_p_row, adj_p_col, adj_p_val);
    cudaEventRecord(e_build, s1);

    // ---- s0: tf32 GEMMs ----
    gemm_tf32_kernel<<<gblocks, 256>>>(x_a, w_self_a, w_rel_p_a, p_self_a, (__half*)p_rels_a,
                                       NNODES);
    gemm_tf32_kernel<<<gblocks, 256>>>(x_p, w_self_p, w_rel_a_p, p_self_p, (__half*)p_rels_p,
                                       NNODES);

    // ---- s0: join build, then fused SpMM+attention+output in one launch ----
    cudaStreamWaitEvent(0, e_build, 0);
    spmm_final2_kernel<<<wblocks2, 256>>>(bias_p, bias_a, out_p, out_a, att_p, att_a);
}